// round 12
// baseline (speedup 1.0000x reference)
#include <cuda_runtime.h>
#include <cstdint>

#define IN_DIM 512
#define HID    512
#define OUT_DIM 256
#define TSTEPS 16
#define M_MAX  32768
#define HL_PITCH 576   // hlist row pitch, mult of 8 -> 1152 B, mult of 16

// Scratch (device globals - allocation-free rule)
__device__ float          g_pre1[(size_t)M_MAX * HID];
__device__ __align__(16) unsigned short g_hlist[(size_t)M_MAX * HL_PITCH];
__device__ unsigned short g_offs[(size_t)M_MAX * 17];

__device__ __forceinline__ void dup2(unsigned long long& d, float s)
{
    asm("mov.b64 %0, {%1, %1};" : "=l"(d) : "f"(s));
}
__device__ __forceinline__ void fma2(unsigned long long& acc,
                                     unsigned long long a, unsigned long long b)
{
    asm("fma.rn.f32x2 %0, %1, %2, %0;" : "+l"(acc) : "l"(a), "l"(b));
}
__device__ __forceinline__ void addx2(unsigned long long& a, unsigned long long w)
{
    asm("add.rn.f32x2 %0, %0, %1;" : "+l"(a) : "l"(w));
}

// ---------------------------------------------------------------------------
// Kernel 1: pre1[m][n] = sum_k x[m][k] * W1[n][k] + b1[n]
// Tile 128M x 256N, 512 threads (16 warps = 4/SMSP), 8Mx8N per thread,
// KC=8 double-buffered. Same per-element k order as before -> bit-identical.
// ---------------------------------------------------------------------------
#define KC 8
#define SPA 132   // A smem pitch
#define SPB 260   // B smem pitch
__global__ void __launch_bounds__(512, 1) gemm1_kernel(
    const float* __restrict__ A,   // x  [M][512]
    const float* __restrict__ W1,  // W1 [512][512] (n-major)
    const float* __restrict__ b1)
{
    __shared__ float As[2][KC][SPA];
    __shared__ float Bs[2][KC][SPB];

    const int tid  = threadIdx.x;
    const int lane = tid & 31;
    const int warp = tid >> 5;   // 0..15
    const int bm   = blockIdx.x * 128;
    const int bn   = blockIdx.y * 256;

    const int lm = lane >> 3;   // 0..3
    const int ln = lane & 7;    // 0..7
    const int row0 = (warp & 3) * 32 + lm * 8;   // M offset in tile
    const int col0 = (warp >> 2) * 64 + ln * 8;  // N offset in tile

    // loaders: A 128x8 (256 float4, threads 0..255), B 256x8 (512 float4, all)
    const int arow = (tid & 255) >> 1;
    const int ak4  = (tid & 1) * 4;
    const int brow = tid >> 1;        // 0..255
    const int bk4  = (tid & 1) * 4;

    const float* Ag = A  + (size_t)(bm + arow) * IN_DIM + ak4;
    const float* Bg = W1 + (size_t)(bn + brow) * IN_DIM + bk4;

    unsigned long long accp[8][4];
#pragma unroll
    for (int i = 0; i < 8; i++)
#pragma unroll
        for (int j = 0; j < 4; j++) accp[i][j] = 0ull;

    float4 pa, pb;

    if (tid < 256) pa = *(const float4*)(Ag);
    pb = *(const float4*)(Bg);
    {
        if (tid < 256) {
            As[0][ak4+0][arow] = pa.x; As[0][ak4+1][arow] = pa.y;
            As[0][ak4+2][arow] = pa.z; As[0][ak4+3][arow] = pa.w;
        }
        Bs[0][bk4+0][brow] = pb.x; Bs[0][bk4+1][brow] = pb.y;
        Bs[0][bk4+2][brow] = pb.z; Bs[0][bk4+3][brow] = pb.w;
    }
    __syncthreads();

    int cur = 0;
    for (int k0 = 0; k0 < IN_DIM; k0 += KC) {
        const int nk = k0 + KC;
        if (nk < IN_DIM) {
            if (tid < 256) pa = *(const float4*)(Ag + nk);
            pb = *(const float4*)(Bg + nk);
        }
#pragma unroll
        for (int kk = 0; kk < KC; kk++) {
            float4 a0 = *(const float4*)&As[cur][kk][row0];
            float4 a1 = *(const float4*)&As[cur][kk][row0 + 4];
            ulonglong2 bq0 = *(const ulonglong2*)&Bs[cur][kk][col0];
            ulonglong2 bq1 = *(const ulonglong2*)&Bs[cur][kk][col0 + 4];
            unsigned long long bq[4] = {bq0.x, bq0.y, bq1.x, bq1.y};
            unsigned long long av2[8];
            dup2(av2[0], a0.x); dup2(av2[1], a0.y);
            dup2(av2[2], a0.z); dup2(av2[3], a0.w);
            dup2(av2[4], a1.x); dup2(av2[5], a1.y);
            dup2(av2[6], a1.z); dup2(av2[7], a1.w);
#pragma unroll
            for (int i = 0; i < 8; i++)
#pragma unroll
                for (int j = 0; j < 4; j++)
                    fma2(accp[i][j], av2[i], bq[j]);
        }
        if (nk < IN_DIM) {
            const int nxt = cur ^ 1;
            if (tid < 256) {
                As[nxt][ak4+0][arow] = pa.x; As[nxt][ak4+1][arow] = pa.y;
                As[nxt][ak4+2][arow] = pa.z; As[nxt][ak4+3][arow] = pa.w;
            }
            Bs[nxt][bk4+0][brow] = pb.x; Bs[nxt][bk4+1][brow] = pb.y;
            Bs[nxt][bk4+2][brow] = pb.z; Bs[nxt][bk4+3][brow] = pb.w;
            __syncthreads();
            cur = nxt;
        }
    }

    // epilogue: unpack, + b1, write 2 float4 per row
    const float4 bb0 = *(const float4*)&b1[bn + col0];
    const float4 bb1 = *(const float4*)&b1[bn + col0 + 4];
#pragma unroll
    for (int i = 0; i < 8; i++) {
        union { unsigned long long u; float2 f; } c0, c1, c2, c3;
        c0.u = accp[i][0]; c1.u = accp[i][1];
        c2.u = accp[i][2]; c3.u = accp[i][3];
        float4 o0 = make_float4(c0.f.x + bb0.x, c0.f.y + bb0.y,
                                c1.f.x + bb0.z, c1.f.y + bb0.w);
        float4 o1 = make_float4(c2.f.x + bb1.x, c2.f.y + bb1.y,
                                c3.f.x + bb1.z, c3.f.y + bb1.w);
        float* Crow = g_pre1 + (size_t)(bm + row0 + i) * HID + bn + col0;
        *(float4*)(Crow)     = o0;
        *(float4*)(Crow + 4) = o1;
    }
}

// ---------------------------------------------------------------------------
// Kernel 2: (round-10 version) 4 rows/block, match-based counting sort,
// buckets padded to multiples of 4 (pad index = 512).
// ---------------------------------------------------------------------------
#define BK_ROWS 4
__global__ void __launch_bounds__(512) bucketize_kernel()
{
    const int h    = threadIdx.x;
    const int lane = h & 31;
    const int warp = h >> 5;
    const int row_base = blockIdx.x * BK_ROWS;

    float p[BK_ROWS];
#pragma unroll
    for (int r = 0; r < BK_ROWS; r++)
        p[r] = g_pre1[(size_t)(row_base + r) * HID + h];

    __shared__ int wcnt[16][17];
    __shared__ int wpre[16][17];
    __shared__ int tot[17];
    __shared__ int base[18];

#pragma unroll
    for (int r = 0; r < BK_ROWS; r++) {
        const int row = row_base + r;

        int k = 0;
        float m = 0.f;
#pragma unroll
        for (int t = 1; t <= TSTEPS; t++) {
            m += p[r];
            if (m > 0.5f) { k = t; break; }
        }

        __syncthreads();
        if (threadIdx.x < 16 * 17) ((int*)wcnt)[threadIdx.x] = 0;
        __syncthreads();

        unsigned peers = __match_any_sync(0xffffffffu, k);
        int rank = __popc(peers & ((1u << lane) - 1u));
        if (rank == 0) wcnt[warp][k] = __popc(peers);
        __syncthreads();

        if (threadIdx.x < 17) {
            int b = threadIdx.x;
            int s = 0;
#pragma unroll
            for (int w = 0; w < 16; w++) { wpre[w][b] = s; s += wcnt[w][b]; }
            tot[b] = s;
        }
        __syncthreads();

        if (warp == 0) {
            int sz = 0;
            if (lane < 16) sz = (tot[lane + 1] + 3) & ~3;
            int s = sz;
#pragma unroll
            for (int d = 1; d < 16; d <<= 1) {
                int t = __shfl_up_sync(0xffffffffu, s, d);
                if (lane >= d) s += t;
            }
            if (lane < 16) base[lane + 1] = s - sz;
            if (lane == 15) base[17] = s;
        }
        __syncthreads();

        unsigned short* hrow = g_hlist + (size_t)row * HL_PITCH;
        if (k > 0) {
            int pos = base[k] + wpre[warp][k] + rank;
            hrow[pos] = (unsigned short)h;
        }
        if (threadIdx.x < 16) {
            int b = threadIdx.x + 1;
            int sz = tot[b];
            int pad = (sz + 3) & ~3;
            for (int q = sz; q < pad; q++) hrow[base[b] + q] = 512;
        }
        if (threadIdx.x < 16)
            g_offs[(size_t)row * 17 + threadIdx.x + 1] = (unsigned short)base[threadIdx.x + 2];
        if (threadIdx.x == 16)
            g_offs[(size_t)row * 17] = 0;
    }
}

// ---------------------------------------------------------------------------
// Kernel 3: (round-10 version) 1024 threads / 32 warps, warp-per-row packed
// gather at pitch 64, single-buffer staging, TT unioned with lists.
// ---------------------------------------------------------------------------
#define W2T_PITCH 64
#define W2T_ROWS  513
#define W2T_BYTES (W2T_ROWS * W2T_PITCH * 4)   // 131328, mult of 16
#define ROWS_PER_ITER 32
#define ROWS_PER_BLOCK 128
#define TT_BYTES     (16 * 32 * 33 * 4)                     // 67584
#define LISTS_BYTES  (ROWS_PER_ITER * HL_PITCH * 2)         // 36864
#define UNION_BYTES  (TT_BYTES > (LISTS_BYTES + ROWS_PER_ITER*17*2) ? \
                      TT_BYTES : (LISTS_BYTES + ROWS_PER_ITER*17*2))
#define P2_SMEM_BYTES (W2T_BYTES + UNION_BYTES)

__global__ void __launch_bounds__(1024, 1) phase2_kernel(
    const float* __restrict__ W2,  // [256][512]
    const float* __restrict__ b2,  // [256]
    float* __restrict__ out)       // [M][256]
{
    extern __shared__ char smem_raw[];
    float* W2Ts = (float*)smem_raw;                                   // [513][64]
    float* TT   = (float*)(smem_raw + W2T_BYTES);                     // staging only
    unsigned short* lists = (unsigned short*)(smem_raw + W2T_BYTES);  // [32][576]
    unsigned short* soffs = (unsigned short*)(smem_raw + W2T_BYTES + LISTS_BYTES);

    const int tid    = threadIdx.x;
    const int w      = tid >> 5;       // 0..31
    const int lane   = tid & 31;
    const int o2     = lane * 2;
    const int o_base = blockIdx.y * 64;

    if (w < 16) {
        float* tile = TT + w * 32 * 33;
#pragma unroll
        for (int tt = 0; tt < 2; tt++) {
            const int t   = w + tt * 16;
            const int oo0 = (t & 1) * 32;
            const int hh0 = (t >> 1) * 32;
#pragma unroll
            for (int r = 0; r < 32; r++) {
                tile[r * 33 + lane] =
                    W2[(size_t)(o_base + oo0 + r) * HID + hh0 + lane];
            }
            __syncwarp();
#pragma unroll
            for (int r2 = 0; r2 < 32; r2++) {
                W2Ts[(hh0 + r2) * W2T_PITCH + oo0 + lane] = tile[lane * 33 + r2];
            }
            __syncwarp();
        }
    }
    if (tid < 64) W2Ts[512 * W2T_PITCH + tid] = 0.f;

    const float2 bb = *(const float2*)&b2[o_base + o2];
    const int row0 = blockIdx.x * ROWS_PER_BLOCK;

    for (int r0 = row0; r0 < row0 + ROWS_PER_BLOCK; r0 += ROWS_PER_ITER) {
        __syncthreads();   // staging/prev-iter readers done
        {
            const uint4* src = (const uint4*)(g_hlist + (size_t)r0 * HL_PITCH);
            uint4* dst = (uint4*)lists;
            for (int i = tid; i < (ROWS_PER_ITER * HL_PITCH) / 8; i += 1024) dst[i] = src[i];
        }
        if (tid < ROWS_PER_ITER * 17)
            soffs[tid] = g_offs[(size_t)r0 * 17 + tid];
        __syncthreads();

        const unsigned short* mylist = lists + w * HL_PITCH;
        const unsigned short* myoff  = soffs + w * 17;
        const float* W2o = W2Ts + o2;

        float2 Ck[16];
        int idx = 0;
#pragma unroll
        for (int k = 1; k <= TSTEPS; k++) {
            const int e = myoff[k];
            unsigned long long accA = 0ull, accB = 0ull;
            for (; idx < e; idx += 4) {
                uint2 pk = *(const uint2*)&mylist[idx];
                int h0 = pk.x & 0xFFFF;
                int h1 = pk.x >> 16;
                int h2 = pk.y & 0xFFFF;
                int h3 = pk.y >> 16;
                unsigned long long w0 = *(const unsigned long long*)&W2o[h0 * W2T_PITCH];
                unsigned long long w1 = *(const unsigned long long*)&W2o[h1 * W2T_PITCH];
                unsigned long long w2 = *(const unsigned long long*)&W2o[h2 * W2T_PITCH];
                unsigned long long w3 = *(const unsigned long long*)&W2o[h3 * W2T_PITCH];
                addx2(accA, w0);
                addx2(accB, w1);
                addx2(accA, w2);
                addx2(accB, w3);
            }
            addx2(accA, accB);
            union { unsigned long long u; float2 f; } cvt;
            cvt.u = accA;
            Ck[k - 1] = cvt.f;
        }

        float m2x = 0.f, m2y = 0.f, scx = 0.f, scy = 0.f;
#pragma unroll
        for (int t = 1; t <= TSTEPS; t++) {
            float yx = 0.f, yy = 0.f;
#pragma unroll
            for (int d = 1; d <= TSTEPS; d++)
                if (t % d == 0) { yx += Ck[d - 1].x; yy += Ck[d - 1].y; }
            m2x = (m2x + yx) + bb.x;
            m2y = (m2y + yy) + bb.y;
            if (m2x > 0.5f) { scx += 1.f; m2x = 0.f; }
            if (m2y > 0.5f) { scy += 1.f; m2y = 0.f; }
        }
        float2 res = make_float2(scx * 0.0625f, scy * 0.0625f);
        *(float2*)&out[(size_t)(r0 + w) * OUT_DIM + o_base + o2] = res;
    }
}

// ---------------------------------------------------------------------------
extern "C" void kernel_launch(void* const* d_in, const int* in_sizes, int n_in,
                              void* d_out, int out_size)
{
    const float* x  = (const float*)d_in[0];
    const float* W1 = (const float*)d_in[1];
    const float* b1 = (const float*)d_in[2];
    const float* W2 = (const float*)d_in[3];
    const float* b2 = (const float*)d_in[4];
    float* out = (float*)d_out;

    const int M = in_sizes[0] / IN_DIM;  // 32768

    dim3 g1(M / 128, HID / 256);
    gemm1_kernel<<<g1, 512>>>(x, W1, b1);

    bucketize_kernel<<<M / BK_ROWS, 512>>>();

    cudaFuncSetAttribute(phase2_kernel,
                         cudaFuncAttributeMaxDynamicSharedMemorySize,
                         P2_SMEM_BYTES);
    dim3 g2(M / ROWS_PER_BLOCK, OUT_DIM / 64);
    phase2_kernel<<<g2, 1024, P2_SMEM_BYTES>>>(W2, b2, out);
}

// round 13
// speedup vs baseline: 1.1161x; 1.1161x over previous
#include <cuda_runtime.h>
#include <cstdint>

#define IN_DIM 512
#define HID    512
#define OUT_DIM 256
#define TSTEPS 16
#define M_MAX  32768
#define HL_PITCH 576   // hlist row pitch, mult of 8 -> 1152 B, mult of 16

// Scratch (device globals - allocation-free rule)
__device__ float          g_pre1[(size_t)M_MAX * HID];
__device__ __align__(16) unsigned short g_hlist[(size_t)M_MAX * HL_PITCH];
__device__ unsigned short g_offs[(size_t)M_MAX * 17];

__device__ __forceinline__ void dup2(unsigned long long& d, float s)
{
    asm("mov.b64 %0, {%1, %1};" : "=l"(d) : "f"(s));
}
__device__ __forceinline__ void fma2(unsigned long long& acc,
                                     unsigned long long a, unsigned long long b)
{
    asm("fma.rn.f32x2 %0, %1, %2, %0;" : "+l"(acc) : "l"(a), "l"(b));
}
__device__ __forceinline__ void addx2(unsigned long long& a, unsigned long long w)
{
    asm("add.rn.f32x2 %0, %0, %1;" : "+l"(a) : "l"(w));
}

// ---------------------------------------------------------------------------
// Kernel 1: (round-10 version) pre1 = x @ W1^T + b1.
// Tile 128M x 256N, 256 threads, 8Mx16N per thread, KC=8 double-buffered,
// packed FFMA2.
// ---------------------------------------------------------------------------
#define KC 8
#define SPA 132   // A smem pitch
#define SPB 260   // B smem pitch
__global__ void __launch_bounds__(256, 1) gemm1_kernel(
    const float* __restrict__ A,   // x  [M][512]
    const float* __restrict__ W1,  // W1 [512][512] (n-major)
    const float* __restrict__ b1)
{
    __shared__ float As[2][KC][SPA];
    __shared__ float Bs[2][KC][SPB];

    const int tid  = threadIdx.x;
    const int lane = tid & 31;
    const int warp = tid >> 5;
    const int bm   = blockIdx.x * 128;
    const int bn   = blockIdx.y * 256;

    const int lm = lane >> 3;   // 0..3
    const int ln = lane & 7;    // 0..7
    const int row0 = (warp & 3) * 32 + lm * 8;
    const int nhalf = (warp >> 2) * 128;

    const int arow = tid >> 1;
    const int ak4  = (tid & 1) * 4;

    const float* Ag  = A  + (size_t)(bm + arow)       * IN_DIM + ak4;
    const float* Bg0 = W1 + (size_t)(bn + arow)       * IN_DIM + ak4;
    const float* Bg1 = W1 + (size_t)(bn + arow + 128) * IN_DIM + ak4;

    unsigned long long accp[8][8];
#pragma unroll
    for (int i = 0; i < 8; i++)
#pragma unroll
        for (int j = 0; j < 8; j++) accp[i][j] = 0ull;

    float4 pa, pb0, pb1;

    pa  = *(const float4*)(Ag);
    pb0 = *(const float4*)(Bg0);
    pb1 = *(const float4*)(Bg1);
    {
        As[0][ak4+0][arow] = pa.x;  As[0][ak4+1][arow] = pa.y;
        As[0][ak4+2][arow] = pa.z;  As[0][ak4+3][arow] = pa.w;
        Bs[0][ak4+0][arow] = pb0.x; Bs[0][ak4+1][arow] = pb0.y;
        Bs[0][ak4+2][arow] = pb0.z; Bs[0][ak4+3][arow] = pb0.w;
        Bs[0][ak4+0][arow+128] = pb1.x; Bs[0][ak4+1][arow+128] = pb1.y;
        Bs[0][ak4+2][arow+128] = pb1.z; Bs[0][ak4+3][arow+128] = pb1.w;
    }
    __syncthreads();

    int cur = 0;
    for (int k0 = 0; k0 < IN_DIM; k0 += KC) {
        const int nk = k0 + KC;
        if (nk < IN_DIM) {
            pa  = *(const float4*)(Ag  + nk);
            pb0 = *(const float4*)(Bg0 + nk);
            pb1 = *(const float4*)(Bg1 + nk);
        }
#pragma unroll
        for (int kk = 0; kk < KC; kk++) {
            float4 a0 = *(const float4*)&As[cur][kk][row0];
            float4 a1 = *(const float4*)&As[cur][kk][row0 + 4];
            unsigned long long bq[8];
#pragma unroll
            for (int q = 0; q < 4; q++) {
                ulonglong2 bl = *(const ulonglong2*)&Bs[cur][kk][nhalf + q * 32 + ln * 4];
                bq[2*q]   = bl.x;
                bq[2*q+1] = bl.y;
            }
            unsigned long long av2[8];
            dup2(av2[0], a0.x); dup2(av2[1], a0.y);
            dup2(av2[2], a0.z); dup2(av2[3], a0.w);
            dup2(av2[4], a1.x); dup2(av2[5], a1.y);
            dup2(av2[6], a1.z); dup2(av2[7], a1.w);
#pragma unroll
            for (int i = 0; i < 8; i++)
#pragma unroll
                for (int j = 0; j < 8; j++)
                    fma2(accp[i][j], av2[i], bq[j]);
        }
        if (nk < IN_DIM) {
            const int nxt = cur ^ 1;
            As[nxt][ak4+0][arow] = pa.x;  As[nxt][ak4+1][arow] = pa.y;
            As[nxt][ak4+2][arow] = pa.z;  As[nxt][ak4+3][arow] = pa.w;
            Bs[nxt][ak4+0][arow] = pb0.x; Bs[nxt][ak4+1][arow] = pb0.y;
            Bs[nxt][ak4+2][arow] = pb0.z; Bs[nxt][ak4+3][arow] = pb0.w;
            Bs[nxt][ak4+0][arow+128] = pb1.x; Bs[nxt][ak4+1][arow+128] = pb1.y;
            Bs[nxt][ak4+2][arow+128] = pb1.z; Bs[nxt][ak4+3][arow+128] = pb1.w;
            __syncthreads();
            cur = nxt;
        }
    }

#pragma unroll
    for (int q = 0; q < 4; q++) {
        const int colq = nhalf + q * 32 + ln * 4;
        const float4 bb = *(const float4*)&b1[bn + colq];
#pragma unroll
        for (int i = 0; i < 8; i++) {
            union { unsigned long long u; float2 f; } c0, c1;
            c0.u = accp[i][2*q];
            c1.u = accp[i][2*q+1];
            float4 o = make_float4(c0.f.x + bb.x, c0.f.y + bb.y,
                                   c1.f.x + bb.z, c1.f.y + bb.w);
            *(float4*)(g_pre1 + (size_t)(bm + row0 + i) * HID + bn + colq) = o;
        }
    }
}

// ---------------------------------------------------------------------------
// Kernel 2 (REWRITTEN): warp-per-row bucketize, zero block barriers.
// Lane l handles h = 16l..16l+15 (ascending-h order preserved within buckets
// -> phase2 sums bit-identical). Histogram in 10-bit packed u64 fields,
// packed warp scan, serial base prefix, scattered u16 writes.
// ---------------------------------------------------------------------------
#define BK_WARPS 16
__global__ void __launch_bounds__(512) bucketize_kernel()
{
    const int lane = threadIdx.x & 31;
    const int warp = threadIdx.x >> 5;
    const int row  = blockIdx.x * BK_WARPS + warp;

    __shared__ int sbase[BK_WARPS][17];

    // load this lane's 16 pre1 values
    const float* pr = g_pre1 + (size_t)row * HID + lane * 16;
    float p[16];
#pragma unroll
    for (int q = 0; q < 4; q++) {
        float4 v = *(const float4*)(pr + q * 4);
        p[q*4+0] = v.x; p[q*4+1] = v.y; p[q*4+2] = v.z; p[q*4+3] = v.w;
    }

    // k per h (identical fp32 cumsum/compare as before) + packed histogram
    // buckets 1..16 -> fields of 10 bits, 4 buckets per u64 (c0..c3)
    unsigned long long c0 = 0, c1 = 0, c2 = 0, c3 = 0;
    int kv[16], ov[16];
#pragma unroll
    for (int j = 0; j < 16; j++) {
        float m = 0.f;
        int k = 0;
#pragma unroll
        for (int t = 1; t <= TSTEPS; t++) {
            m += p[j];
            if (m > 0.5f && k == 0) k = t;
        }
        kv[j] = k;
        ov[j] = 0;
        if (k > 0) {
            const int idx = k - 1;
            const int word = idx >> 2;
            const int shift = (idx & 3) * 10;
            unsigned long long curw =
                (word == 0) ? c0 : (word == 1) ? c1 : (word == 2) ? c2 : c3;
            ov[j] = (int)((curw >> shift) & 1023u);
            const unsigned long long inc = 1ull << shift;
            if (word == 0) c0 += inc;
            else if (word == 1) c1 += inc;
            else if (word == 2) c2 += inc;
            else c3 += inc;
        }
    }

    // inclusive warp scan of packed counters (fields can't overflow: <=512 < 1024)
    unsigned long long s0 = c0, s1 = c1, s2 = c2, s3 = c3;
#pragma unroll
    for (int d = 1; d < 32; d <<= 1) {
        unsigned long long u0 = __shfl_up_sync(0xffffffffu, s0, d);
        unsigned long long u1 = __shfl_up_sync(0xffffffffu, s1, d);
        unsigned long long u2 = __shfl_up_sync(0xffffffffu, s2, d);
        unsigned long long u3 = __shfl_up_sync(0xffffffffu, s3, d);
        if (lane >= d) { s0 += u0; s1 += u1; s2 += u2; s3 += u3; }
    }
    const unsigned long long e0 = s0 - c0, e1 = s1 - c1,
                             e2 = s2 - c2, e3 = s3 - c3;   // lane-exclusive
    const unsigned long long t0 = __shfl_sync(0xffffffffu, s0, 31);
    const unsigned long long t1 = __shfl_sync(0xffffffffu, s1, 31);
    const unsigned long long t2 = __shfl_sync(0xffffffffu, s2, 31);
    const unsigned long long t3 = __shfl_sync(0xffffffffu, s3, 31);

    // serial base prefix over buckets (compile-time field extraction)
    int run = 0;
    int base_l1 = 0;   // base[lane+1]           (lane < 16)
    int offs_l  = 0;   // base[lane+2] for offs  (lane < 15); lane 15 -> end
#pragma unroll
    for (int b = 1; b <= 16; b++) {
        const int idx = b - 1;
        const unsigned long long tw =
            ((idx >> 2) == 0) ? t0 : ((idx >> 2) == 1) ? t1 :
            ((idx >> 2) == 2) ? t2 : t3;                      // compile-time pick
        const int tot = (int)((tw >> ((idx & 3) * 10)) & 1023u);
        if (b == lane + 1) base_l1 = run;
        if (b == lane + 2) offs_l  = run;
        run += (tot + 3) & ~3;
    }
    if (lane == 15) offs_l = run;   // base[17] = padded end

    if (lane < 16) sbase[warp][lane + 1] = base_l1;
    __syncwarp();

    unsigned short* hrow = g_hlist + (size_t)row * HL_PITCH;

    // scatter entries: pos = base[k] + lane_exclusive_prefix[k] + local ordinal
#pragma unroll
    for (int j = 0; j < 16; j++) {
        const int k = kv[j];
        if (k > 0) {
            const int idx = k - 1;
            const int word = idx >> 2;
            const unsigned long long ew =
                (word == 0) ? e0 : (word == 1) ? e1 : (word == 2) ? e2 : e3;
            const int lpre = (int)((ew >> ((idx & 3) * 10)) & 1023u);
            const int pos = sbase[warp][k] + lpre + ov[j];
            hrow[pos] = (unsigned short)(lane * 16 + j);
        }
    }

    // pads + offsets
    if (lane < 16) {
        const int idx = lane;          // bucket b = lane+1
        const int word = idx >> 2;
        const unsigned long long tw =
            (word == 0) ? t0 : (word == 1) ? t1 : (word == 2) ? t2 : t3;
        const int tot = (int)((tw >> ((idx & 3) * 10)) & 1023u);
        const int pad = (tot + 3) & ~3;
        for (int q = tot; q < pad; q++) hrow[base_l1 + q] = 512;
        g_offs[(size_t)row * 17 + lane + 1] = (unsigned short)offs_l;
    }
    if (lane == 16) g_offs[(size_t)row * 17] = 0;
}

// ---------------------------------------------------------------------------
// Kernel 3: (round-10 version) 1024 threads / 32 warps, warp-per-row packed
// gather at pitch 64, single-buffer staging, TT unioned with lists.
// ---------------------------------------------------------------------------
#define W2T_PITCH 64
#define W2T_ROWS  513
#define W2T_BYTES (W2T_ROWS * W2T_PITCH * 4)   // 131328, mult of 16
#define ROWS_PER_ITER 32
#define ROWS_PER_BLOCK 128
#define TT_BYTES     (16 * 32 * 33 * 4)                     // 67584
#define LISTS_BYTES  (ROWS_PER_ITER * HL_PITCH * 2)         // 36864
#define UNION_BYTES  (TT_BYTES > (LISTS_BYTES + ROWS_PER_ITER*17*2) ? \
                      TT_BYTES : (LISTS_BYTES + ROWS_PER_ITER*17*2))
#define P2_SMEM_BYTES (W2T_BYTES + UNION_BYTES)

__global__ void __launch_bounds__(1024, 1) phase2_kernel(
    const float* __restrict__ W2,  // [256][512]
    const float* __restrict__ b2,  // [256]
    float* __restrict__ out)       // [M][256]
{
    extern __shared__ char smem_raw[];
    float* W2Ts = (float*)smem_raw;                                   // [513][64]
    float* TT   = (float*)(smem_raw + W2T_BYTES);                     // staging only
    unsigned short* lists = (unsigned short*)(smem_raw + W2T_BYTES);  // [32][576]
    unsigned short* soffs = (unsigned short*)(smem_raw + W2T_BYTES + LISTS_BYTES);

    const int tid    = threadIdx.x;
    const int w      = tid >> 5;       // 0..31
    const int lane   = tid & 31;
    const int o2     = lane * 2;
    const int o_base = blockIdx.y * 64;

    if (w < 16) {
        float* tile = TT + w * 32 * 33;
#pragma unroll
        for (int tt = 0; tt < 2; tt++) {
            const int t   = w + tt * 16;
            const int oo0 = (t & 1) * 32;
            const int hh0 = (t >> 1) * 32;
#pragma unroll
            for (int r = 0; r < 32; r++) {
                tile[r * 33 + lane] =
                    W2[(size_t)(o_base + oo0 + r) * HID + hh0 + lane];
            }
            __syncwarp();
#pragma unroll
            for (int r2 = 0; r2 < 32; r2++) {
                W2Ts[(hh0 + r2) * W2T_PITCH + oo0 + lane] = tile[lane * 33 + r2];
            }
            __syncwarp();
        }
    }
    if (tid < 64) W2Ts[512 * W2T_PITCH + tid] = 0.f;

    const float2 bb = *(const float2*)&b2[o_base + o2];
    const int row0 = blockIdx.x * ROWS_PER_BLOCK;

    for (int r0 = row0; r0 < row0 + ROWS_PER_BLOCK; r0 += ROWS_PER_ITER) {
        __syncthreads();   // staging/prev-iter readers done
        {
            const uint4* src = (const uint4*)(g_hlist + (size_t)r0 * HL_PITCH);
            uint4* dst = (uint4*)lists;
            for (int i = tid; i < (ROWS_PER_ITER * HL_PITCH) / 8; i += 1024) dst[i] = src[i];
        }
        if (tid < ROWS_PER_ITER * 17)
            soffs[tid] = g_offs[(size_t)r0 * 17 + tid];
        __syncthreads();

        const unsigned short* mylist = lists + w * HL_PITCH;
        const unsigned short* myoff  = soffs + w * 17;
        const float* W2o = W2Ts + o2;

        float2 Ck[16];
        int idx = 0;
#pragma unroll
        for (int k = 1; k <= TSTEPS; k++) {
            const int e = myoff[k];
            unsigned long long accA = 0ull, accB = 0ull;
            for (; idx < e; idx += 4) {
                uint2 pk = *(const uint2*)&mylist[idx];
                int h0 = pk.x & 0xFFFF;
                int h1 = pk.x >> 16;
                int h2 = pk.y & 0xFFFF;
                int h3 = pk.y >> 16;
                unsigned long long w0 = *(const unsigned long long*)&W2o[h0 * W2T_PITCH];
                unsigned long long w1 = *(const unsigned long long*)&W2o[h1 * W2T_PITCH];
                unsigned long long w2 = *(const unsigned long long*)&W2o[h2 * W2T_PITCH];
                unsigned long long w3 = *(const unsigned long long*)&W2o[h3 * W2T_PITCH];
                addx2(accA, w0);
                addx2(accB, w1);
                addx2(accA, w2);
                addx2(accB, w3);
            }
            addx2(accA, accB);
            union { unsigned long long u; float2 f; } cvt;
            cvt.u = accA;
            Ck[k - 1] = cvt.f;
        }

        float m2x = 0.f, m2y = 0.f, scx = 0.f, scy = 0.f;
#pragma unroll
        for (int t = 1; t <= TSTEPS; t++) {
            float yx = 0.f, yy = 0.f;
#pragma unroll
            for (int d = 1; d <= TSTEPS; d++)
                if (t % d == 0) { yx += Ck[d - 1].x; yy += Ck[d - 1].y; }
            m2x = (m2x + yx) + bb.x;
            m2y = (m2y + yy) + bb.y;
            if (m2x > 0.5f) { scx += 1.f; m2x = 0.f; }
            if (m2y > 0.5f) { scy += 1.f; m2y = 0.f; }
        }
        float2 res = make_float2(scx * 0.0625f, scy * 0.0625f);
        *(float2*)&out[(size_t)(r0 + w) * OUT_DIM + o_base + o2] = res;
    }
}

// ---------------------------------------------------------------------------
extern "C" void kernel_launch(void* const* d_in, const int* in_sizes, int n_in,
                              void* d_out, int out_size)
{
    const float* x  = (const float*)d_in[0];
    const float* W1 = (const float*)d_in[1];
    const float* b1 = (const float*)d_in[2];
    const float* W2 = (const float*)d_in[3];
    const float* b2 = (const float*)d_in[4];
    float* out = (float*)d_out;

    const int M = in_sizes[0] / IN_DIM;  // 32768

    dim3 g1(M / 128, HID / 256);
    gemm1_kernel<<<g1, 256>>>(x, W1, b1);

    bucketize_kernel<<<M / BK_WARPS, 512>>>();

    cudaFuncSetAttribute(phase2_kernel,
                         cudaFuncAttributeMaxDynamicSharedMemorySize,
                         P2_SMEM_BYTES);
    dim3 g2(M / ROWS_PER_BLOCK, OUT_DIM / 64);
    phase2_kernel<<<g2, 1024, P2_SMEM_BYTES>>>(W2, b2, out);
}

// round 14
// speedup vs baseline: 1.1993x; 1.0746x over previous
#include <cuda_runtime.h>
#include <cstdint>

#define IN_DIM 512
#define HID    512
#define OUT_DIM 256
#define TSTEPS 16
#define M_MAX  32768
#define HL_PITCH 576   // hlist row pitch, mult of 8 -> 1152 B, mult of 16
#define OF_PITCH 32    // offs row pitch (u16) -> 64 B aligned rows

// Scratch (device globals - allocation-free rule)
__device__ float          g_pre1[(size_t)M_MAX * HID];
__device__ __align__(16) unsigned short g_hlist[(size_t)M_MAX * HL_PITCH];
__device__ __align__(16) unsigned short g_offs[(size_t)M_MAX * OF_PITCH];

__device__ __forceinline__ void dup2(unsigned long long& d, float s)
{
    asm("mov.b64 %0, {%1, %1};" : "=l"(d) : "f"(s));
}
__device__ __forceinline__ void fma2(unsigned long long& acc,
                                     unsigned long long a, unsigned long long b)
{
    asm("fma.rn.f32x2 %0, %1, %2, %0;" : "+l"(acc) : "l"(a), "l"(b));
}
__device__ __forceinline__ void addx2(unsigned long long& a, unsigned long long w)
{
    asm("add.rn.f32x2 %0, %0, %1;" : "+l"(a) : "l"(w));
}

// ---------------------------------------------------------------------------
// Kernel 1: (round-10 version, unchanged) pre1 = x @ W1^T + b1.
// Tile 128M x 256N, 256 threads, 8Mx16N per thread, KC=8 double-buffered.
// ---------------------------------------------------------------------------
#define KC 8
#define SPA 132   // A smem pitch
#define SPB 260   // B smem pitch
__global__ void __launch_bounds__(256, 1) gemm1_kernel(
    const float* __restrict__ A,   // x  [M][512]
    const float* __restrict__ W1,  // W1 [512][512] (n-major)
    const float* __restrict__ b1)
{
    __shared__ float As[2][KC][SPA];
    __shared__ float Bs[2][KC][SPB];

    const int tid  = threadIdx.x;
    const int lane = tid & 31;
    const int warp = tid >> 5;
    const int bm   = blockIdx.x * 128;
    const int bn   = blockIdx.y * 256;

    const int lm = lane >> 3;
    const int ln = lane & 7;
    const int row0 = (warp & 3) * 32 + lm * 8;
    const int nhalf = (warp >> 2) * 128;

    const int arow = tid >> 1;
    const int ak4  = (tid & 1) * 4;

    const float* Ag  = A  + (size_t)(bm + arow)       * IN_DIM + ak4;
    const float* Bg0 = W1 + (size_t)(bn + arow)       * IN_DIM + ak4;
    const float* Bg1 = W1 + (size_t)(bn + arow + 128) * IN_DIM + ak4;

    unsigned long long accp[8][8];
#pragma unroll
    for (int i = 0; i < 8; i++)
#pragma unroll
        for (int j = 0; j < 8; j++) accp[i][j] = 0ull;

    float4 pa, pb0, pb1;

    pa  = *(const float4*)(Ag);
    pb0 = *(const float4*)(Bg0);
    pb1 = *(const float4*)(Bg1);
    {
        As[0][ak4+0][arow] = pa.x;  As[0][ak4+1][arow] = pa.y;
        As[0][ak4+2][arow] = pa.z;  As[0][ak4+3][arow] = pa.w;
        Bs[0][ak4+0][arow] = pb0.x; Bs[0][ak4+1][arow] = pb0.y;
        Bs[0][ak4+2][arow] = pb0.z; Bs[0][ak4+3][arow] = pb0.w;
        Bs[0][ak4+0][arow+128] = pb1.x; Bs[0][ak4+1][arow+128] = pb1.y;
        Bs[0][ak4+2][arow+128] = pb1.z; Bs[0][ak4+3][arow+128] = pb1.w;
    }
    __syncthreads();

    int cur = 0;
    for (int k0 = 0; k0 < IN_DIM; k0 += KC) {
        const int nk = k0 + KC;
        if (nk < IN_DIM) {
            pa  = *(const float4*)(Ag  + nk);
            pb0 = *(const float4*)(Bg0 + nk);
            pb1 = *(const float4*)(Bg1 + nk);
        }
#pragma unroll
        for (int kk = 0; kk < KC; kk++) {
            float4 a0 = *(const float4*)&As[cur][kk][row0];
            float4 a1 = *(const float4*)&As[cur][kk][row0 + 4];
            unsigned long long bq[8];
#pragma unroll
            for (int q = 0; q < 4; q++) {
                ulonglong2 bl = *(const ulonglong2*)&Bs[cur][kk][nhalf + q * 32 + ln * 4];
                bq[2*q]   = bl.x;
                bq[2*q+1] = bl.y;
            }
            unsigned long long av2[8];
            dup2(av2[0], a0.x); dup2(av2[1], a0.y);
            dup2(av2[2], a0.z); dup2(av2[3], a0.w);
            dup2(av2[4], a1.x); dup2(av2[5], a1.y);
            dup2(av2[6], a1.z); dup2(av2[7], a1.w);
#pragma unroll
            for (int i = 0; i < 8; i++)
#pragma unroll
                for (int j = 0; j < 8; j++)
                    fma2(accp[i][j], av2[i], bq[j]);
        }
        if (nk < IN_DIM) {
            const int nxt = cur ^ 1;
            As[nxt][ak4+0][arow] = pa.x;  As[nxt][ak4+1][arow] = pa.y;
            As[nxt][ak4+2][arow] = pa.z;  As[nxt][ak4+3][arow] = pa.w;
            Bs[nxt][ak4+0][arow] = pb0.x; Bs[nxt][ak4+1][arow] = pb0.y;
            Bs[nxt][ak4+2][arow] = pb0.z; Bs[nxt][ak4+3][arow] = pb0.w;
            Bs[nxt][ak4+0][arow+128] = pb1.x; Bs[nxt][ak4+1][arow+128] = pb1.y;
            Bs[nxt][ak4+2][arow+128] = pb1.z; Bs[nxt][ak4+3][arow+128] = pb1.w;
            __syncthreads();
            cur = nxt;
        }
    }

#pragma unroll
    for (int q = 0; q < 4; q++) {
        const int colq = nhalf + q * 32 + ln * 4;
        const float4 bb = *(const float4*)&b1[bn + colq];
#pragma unroll
        for (int i = 0; i < 8; i++) {
            union { unsigned long long u; float2 f; } c0, c1;
            c0.u = accp[i][2*q];
            c1.u = accp[i][2*q+1];
            float4 o = make_float4(c0.f.x + bb.x, c0.f.y + bb.y,
                                   c1.f.x + bb.z, c1.f.y + bb.w);
            *(float4*)(g_pre1 + (size_t)(bm + row0 + i) * HID + bn + colq) = o;
        }
    }
}

// ---------------------------------------------------------------------------
// Kernel 2: (round-10 block version, reverted) 4 rows/block, match-based
// counting sort, buckets padded to multiples of 4 (pad index = 512).
// Only change: g_offs pitch 17 -> 32 for aligned vector reads in phase2.
// ---------------------------------------------------------------------------
#define BK_ROWS 4
__global__ void __launch_bounds__(512) bucketize_kernel()
{
    const int h    = threadIdx.x;
    const int lane = h & 31;
    const int warp = h >> 5;
    const int row_base = blockIdx.x * BK_ROWS;

    float p[BK_ROWS];
#pragma unroll
    for (int r = 0; r < BK_ROWS; r++)
        p[r] = g_pre1[(size_t)(row_base + r) * HID + h];

    __shared__ int wcnt[16][17];
    __shared__ int wpre[16][17];
    __shared__ int tot[17];
    __shared__ int base[18];

#pragma unroll
    for (int r = 0; r < BK_ROWS; r++) {
        const int row = row_base + r;

        int k = 0;
        float m = 0.f;
#pragma unroll
        for (int t = 1; t <= TSTEPS; t++) {
            m += p[r];
            if (m > 0.5f) { k = t; break; }
        }

        __syncthreads();
        if (threadIdx.x < 16 * 17) ((int*)wcnt)[threadIdx.x] = 0;
        __syncthreads();

        unsigned peers = __match_any_sync(0xffffffffu, k);
        int rank = __popc(peers & ((1u << lane) - 1u));
        if (rank == 0) wcnt[warp][k] = __popc(peers);
        __syncthreads();

        if (threadIdx.x < 17) {
            int b = threadIdx.x;
            int s = 0;
#pragma unroll
            for (int w = 0; w < 16; w++) { wpre[w][b] = s; s += wcnt[w][b]; }
            tot[b] = s;
        }
        __syncthreads();

        if (warp == 0) {
            int sz = 0;
            if (lane < 16) sz = (tot[lane + 1] + 3) & ~3;
            int s = sz;
#pragma unroll
            for (int d = 1; d < 16; d <<= 1) {
                int t = __shfl_up_sync(0xffffffffu, s, d);
                if (lane >= d) s += t;
            }
            if (lane < 16) base[lane + 1] = s - sz;
            if (lane == 15) base[17] = s;
        }
        __syncthreads();

        unsigned short* hrow = g_hlist + (size_t)row * HL_PITCH;
        if (k > 0) {
            int pos = base[k] + wpre[warp][k] + rank;
            hrow[pos] = (unsigned short)h;
        }
        if (threadIdx.x < 16) {
            int b = threadIdx.x + 1;
            int sz = tot[b];
            int pad = (sz + 3) & ~3;
            for (int q = sz; q < pad; q++) hrow[base[b] + q] = 512;
        }
        if (threadIdx.x < 16)
            g_offs[(size_t)row * OF_PITCH + threadIdx.x + 1] =
                (unsigned short)base[threadIdx.x + 2];
        if (threadIdx.x == 16)
            g_offs[(size_t)row * OF_PITCH] = 0;
    }
}

// ---------------------------------------------------------------------------
// Kernel 3: 1024 threads / 32 warps. After W2Ts staging, warps are FULLY
// INDEPENDENT: indices read straight from global via uniform LDG.64
// broadcasts (prefetched 1 chunk ahead), offsets via 3 vector LDGs.
// No list staging, no barriers in the main loop.
// ---------------------------------------------------------------------------
#define W2T_PITCH 64
#define W2T_ROWS  513
#define W2T_BYTES (W2T_ROWS * W2T_PITCH * 4)   // 131328
#define TT_BYTES  (16 * 32 * 33 * 4)           // 67584
#define ROWS_PER_BLOCK 128
#define P2_SMEM_BYTES (W2T_BYTES + TT_BYTES)   // 198912

__global__ void __launch_bounds__(1024, 1) phase2_kernel(
    const float* __restrict__ W2,  // [256][512]
    const float* __restrict__ b2,  // [256]
    float* __restrict__ out)       // [M][256]
{
    extern __shared__ char smem_raw[];
    float* W2Ts = (float*)smem_raw;                 // [513][64]
    float* TT   = (float*)(smem_raw + W2T_BYTES);   // transpose staging only

    const int tid    = threadIdx.x;
    const int w      = tid >> 5;       // 0..31
    const int lane   = tid & 31;
    const int o2     = lane * 2;
    const int o_base = blockIdx.y * 64;

    // Stage W2^T via tiled transpose (warps 0..15)
    if (w < 16) {
        float* tile = TT + w * 32 * 33;
#pragma unroll
        for (int tt = 0; tt < 2; tt++) {
            const int t   = w + tt * 16;
            const int oo0 = (t & 1) * 32;
            const int hh0 = (t >> 1) * 32;
#pragma unroll
            for (int r = 0; r < 32; r++) {
                tile[r * 33 + lane] =
                    W2[(size_t)(o_base + oo0 + r) * HID + hh0 + lane];
            }
            __syncwarp();
#pragma unroll
            for (int r2 = 0; r2 < 32; r2++) {
                W2Ts[(hh0 + r2) * W2T_PITCH + oo0 + lane] = tile[lane * 33 + r2];
            }
            __syncwarp();
        }
    }
    if (tid < 64) W2Ts[512 * W2T_PITCH + tid] = 0.f;
    __syncthreads();   // W2Ts ready; warps run free from here

    const float2 bb = *(const float2*)&b2[o_base + o2];
    const float* W2o = W2Ts + o2;
    const int row0 = blockIdx.x * ROWS_PER_BLOCK;

#pragma unroll
    for (int rr = 0; rr < ROWS_PER_BLOCK / 32; rr++) {
        const int row = row0 + rr * 32 + w;
        const unsigned short* ml = g_hlist + (size_t)row * HL_PITCH;

        // offsets: 3 uniform vector loads (broadcast), compile-time extraction
        const uint4 oa = *(const uint4*)(g_offs + (size_t)row * OF_PITCH);       // u16 0..7
        const uint4 ob = *(const uint4*)(g_offs + (size_t)row * OF_PITCH + 8);   // u16 8..15
        const unsigned int oc = *(const unsigned int*)(g_offs + (size_t)row * OF_PITCH + 16); // u16 16
        const unsigned int ow[9] = {oa.x, oa.y, oa.z, oa.w, ob.x, ob.y, ob.z, ob.w, oc};

        float2 Ck[16];
        int idx = 0;
        uint2 pk = *(const uint2*)ml;   // prefetch first chunk (always in-bounds)
#pragma unroll
        for (int k = 1; k <= TSTEPS; k++) {
            const int e = (int)((ow[k >> 1] >> ((k & 1) * 16)) & 0xFFFFu);
            unsigned long long accA = 0ull, accB = 0ull;
            for (; idx < e; idx += 4) {
                const uint2 cur = pk;
                pk = *(const uint2*)&ml[idx + 4];   // prefetch next (pitch-bounded)
                int h0 = cur.x & 0xFFFF;
                int h1 = cur.x >> 16;
                int h2 = cur.y & 0xFFFF;
                int h3 = cur.y >> 16;
                unsigned long long w0 = *(const unsigned long long*)&W2o[h0 * W2T_PITCH];
                unsigned long long w1 = *(const unsigned long long*)&W2o[h1 * W2T_PITCH];
                unsigned long long w2 = *(const unsigned long long*)&W2o[h2 * W2T_PITCH];
                unsigned long long w3 = *(const unsigned long long*)&W2o[h3 * W2T_PITCH];
                addx2(accA, w0);
                addx2(accB, w1);
                addx2(accA, w2);
                addx2(accB, w3);
            }
            addx2(accA, accB);
            union { unsigned long long u; float2 f; } cvt;
            cvt.u = accA;
            Ck[k - 1] = cvt.f;
        }

        float m2x = 0.f, m2y = 0.f, scx = 0.f, scy = 0.f;
#pragma unroll
        for (int t = 1; t <= TSTEPS; t++) {
            float yx = 0.f, yy = 0.f;
#pragma unroll
            for (int d = 1; d <= TSTEPS; d++)
                if (t % d == 0) { yx += Ck[d - 1].x; yy += Ck[d - 1].y; }
            m2x = (m2x + yx) + bb.x;
            m2y = (m2y + yy) + bb.y;
            if (m2x > 0.5f) { scx += 1.f; m2x = 0.f; }
            if (m2y > 0.5f) { scy += 1.f; m2y = 0.f; }
        }
        float2 res = make_float2(scx * 0.0625f, scy * 0.0625f);
        *(float2*)&out[(size_t)row * OUT_DIM + o_base + o2] = res;
    }
}

// ---------------------------------------------------------------------------
extern "C" void kernel_launch(void* const* d_in, const int* in_sizes, int n_in,
                              void* d_out, int out_size)
{
    const float* x  = (const float*)d_in[0];
    const float* W1 = (const float*)d_in[1];
    const float* b1 = (const float*)d_in[2];
    const float* W2 = (const float*)d_in[3];
    const float* b2 = (const float*)d_in[4];
    float* out = (float*)d_out;

    const int M = in_sizes[0] / IN_DIM;  // 32768

    dim3 g1(M / 128, HID / 256);
    gemm1_kernel<<<g1, 256>>>(x, W1, b1);

    bucketize_kernel<<<M / BK_ROWS, 512>>>();

    cudaFuncSetAttribute(phase2_kernel,
                         cudaFuncAttributeMaxDynamicSharedMemorySize,
                         P2_SMEM_BYTES);
    dim3 g2(M / ROWS_PER_BLOCK, OUT_DIM / 64);
    phase2_kernel<<<g2, 1024, P2_SMEM_BYTES>>>(W2, b2, out);
}

// round 15
// speedup vs baseline: 1.2431x; 1.0365x over previous
#include <cuda_runtime.h>
#include <cstdint>

#define IN_DIM 512
#define HID    512
#define OUT_DIM 256
#define TSTEPS 16
#define M_MAX  32768
#define HL_PITCH 576   // hlist row pitch, mult of 8 -> 1152 B, mult of 16
#define OF_PITCH 32    // offs row pitch (u16) -> 64 B aligned rows
#define M_CHUNK 16384  // pipeline chunk (2 chunks)

// Scratch (device globals - allocation-free rule)
__device__ float          g_pre1[(size_t)M_MAX * HID];
__device__ __align__(16) unsigned short g_hlist[(size_t)M_MAX * HL_PITCH];
__device__ __align__(16) unsigned short g_offs[(size_t)M_MAX * OF_PITCH];

__device__ __forceinline__ void dup2(unsigned long long& d, float s)
{
    asm("mov.b64 %0, {%1, %1};" : "=l"(d) : "f"(s));
}
__device__ __forceinline__ void fma2(unsigned long long& acc,
                                     unsigned long long a, unsigned long long b)
{
    asm("fma.rn.f32x2 %0, %1, %2, %0;" : "+l"(acc) : "l"(a), "l"(b));
}
__device__ __forceinline__ void addx2(unsigned long long& a, unsigned long long w)
{
    asm("add.rn.f32x2 %0, %0, %1;" : "+l"(a) : "l"(w));
}

// ---------------------------------------------------------------------------
// Kernel 1: pre1 = x @ W1^T + b1. (round-10 version + m0 chunk offset)
// Tile 128M x 256N, 256 threads, 8Mx16N per thread, KC=8 double-buffered.
// ---------------------------------------------------------------------------
#define KC 8
#define SPA 132
#define SPB 260
__global__ void __launch_bounds__(256, 1) gemm1_kernel(
    const float* __restrict__ A,
    const float* __restrict__ W1,
    const float* __restrict__ b1,
    int m0)
{
    __shared__ float As[2][KC][SPA];
    __shared__ float Bs[2][KC][SPB];

    const int tid  = threadIdx.x;
    const int lane = tid & 31;
    const int warp = tid >> 5;
    const int bm   = m0 + blockIdx.x * 128;
    const int bn   = blockIdx.y * 256;

    const int lm = lane >> 3;
    const int ln = lane & 7;
    const int row0 = (warp & 3) * 32 + lm * 8;
    const int nhalf = (warp >> 2) * 128;

    const int arow = tid >> 1;
    const int ak4  = (tid & 1) * 4;

    const float* Ag  = A  + (size_t)(bm + arow)       * IN_DIM + ak4;
    const float* Bg0 = W1 + (size_t)(bn + arow)       * IN_DIM + ak4;
    const float* Bg1 = W1 + (size_t)(bn + arow + 128) * IN_DIM + ak4;

    unsigned long long accp[8][8];
#pragma unroll
    for (int i = 0; i < 8; i++)
#pragma unroll
        for (int j = 0; j < 8; j++) accp[i][j] = 0ull;

    float4 pa, pb0, pb1;

    pa  = *(const float4*)(Ag);
    pb0 = *(const float4*)(Bg0);
    pb1 = *(const float4*)(Bg1);
    {
        As[0][ak4+0][arow] = pa.x;  As[0][ak4+1][arow] = pa.y;
        As[0][ak4+2][arow] = pa.z;  As[0][ak4+3][arow] = pa.w;
        Bs[0][ak4+0][arow] = pb0.x; Bs[0][ak4+1][arow] = pb0.y;
        Bs[0][ak4+2][arow] = pb0.z; Bs[0][ak4+3][arow] = pb0.w;
        Bs[0][ak4+0][arow+128] = pb1.x; Bs[0][ak4+1][arow+128] = pb1.y;
        Bs[0][ak4+2][arow+128] = pb1.z; Bs[0][ak4+3][arow+128] = pb1.w;
    }
    __syncthreads();

    int cur = 0;
    for (int k0 = 0; k0 < IN_DIM; k0 += KC) {
        const int nk = k0 + KC;
        if (nk < IN_DIM) {
            pa  = *(const float4*)(Ag  + nk);
            pb0 = *(const float4*)(Bg0 + nk);
            pb1 = *(const float4*)(Bg1 + nk);
        }
#pragma unroll
        for (int kk = 0; kk < KC; kk++) {
            float4 a0 = *(const float4*)&As[cur][kk][row0];
            float4 a1 = *(const float4*)&As[cur][kk][row0 + 4];
            unsigned long long bq[8];
#pragma unroll
            for (int q = 0; q < 4; q++) {
                ulonglong2 bl = *(const ulonglong2*)&Bs[cur][kk][nhalf + q * 32 + ln * 4];
                bq[2*q]   = bl.x;
                bq[2*q+1] = bl.y;
            }
            unsigned long long av2[8];
            dup2(av2[0], a0.x); dup2(av2[1], a0.y);
            dup2(av2[2], a0.z); dup2(av2[3], a0.w);
            dup2(av2[4], a1.x); dup2(av2[5], a1.y);
            dup2(av2[6], a1.z); dup2(av2[7], a1.w);
#pragma unroll
            for (int i = 0; i < 8; i++)
#pragma unroll
                for (int j = 0; j < 8; j++)
                    fma2(accp[i][j], av2[i], bq[j]);
        }
        if (nk < IN_DIM) {
            const int nxt = cur ^ 1;
            As[nxt][ak4+0][arow] = pa.x;  As[nxt][ak4+1][arow] = pa.y;
            As[nxt][ak4+2][arow] = pa.z;  As[nxt][ak4+3][arow] = pa.w;
            Bs[nxt][ak4+0][arow] = pb0.x; Bs[nxt][ak4+1][arow] = pb0.y;
            Bs[nxt][ak4+2][arow] = pb0.z; Bs[nxt][ak4+3][arow] = pb0.w;
            Bs[nxt][ak4+0][arow+128] = pb1.x; Bs[nxt][ak4+1][arow+128] = pb1.y;
            Bs[nxt][ak4+2][arow+128] = pb1.z; Bs[nxt][ak4+3][arow+128] = pb1.w;
            __syncthreads();
            cur = nxt;
        }
    }

#pragma unroll
    for (int q = 0; q < 4; q++) {
        const int colq = nhalf + q * 32 + ln * 4;
        const float4 bb = *(const float4*)&b1[bn + colq];
#pragma unroll
        for (int i = 0; i < 8; i++) {
            union { unsigned long long u; float2 f; } c0, c1;
            c0.u = accp[i][2*q];
            c1.u = accp[i][2*q+1];
            float4 o = make_float4(c0.f.x + bb.x, c0.f.y + bb.y,
                                   c1.f.x + bb.z, c1.f.y + bb.w);
            *(float4*)(g_pre1 + (size_t)(bm + row0 + i) * HID + bn + colq) = o;
        }
    }
}

// ---------------------------------------------------------------------------
// Kernel 2: (round-10 block version + m0) 4 rows/block, counting sort,
// buckets padded to multiples of 4 (pad index = 512).
// ---------------------------------------------------------------------------
#define BK_ROWS 4
__global__ void __launch_bounds__(512) bucketize_kernel(int m0)
{
    const int h    = threadIdx.x;
    const int lane = h & 31;
    const int warp = h >> 5;
    const int row_base = m0 + blockIdx.x * BK_ROWS;

    float p[BK_ROWS];
#pragma unroll
    for (int r = 0; r < BK_ROWS; r++)
        p[r] = g_pre1[(size_t)(row_base + r) * HID + h];

    __shared__ int wcnt[16][17];
    __shared__ int wpre[16][17];
    __shared__ int tot[17];
    __shared__ int base[18];

#pragma unroll
    for (int r = 0; r < BK_ROWS; r++) {
        const int row = row_base + r;

        int k = 0;
        float m = 0.f;
#pragma unroll
        for (int t = 1; t <= TSTEPS; t++) {
            m += p[r];
            if (m > 0.5f) { k = t; break; }
        }

        __syncthreads();
        if (threadIdx.x < 16 * 17) ((int*)wcnt)[threadIdx.x] = 0;
        __syncthreads();

        unsigned peers = __match_any_sync(0xffffffffu, k);
        int rank = __popc(peers & ((1u << lane) - 1u));
        if (rank == 0) wcnt[warp][k] = __popc(peers);
        __syncthreads();

        if (threadIdx.x < 17) {
            int b = threadIdx.x;
            int s = 0;
#pragma unroll
            for (int w = 0; w < 16; w++) { wpre[w][b] = s; s += wcnt[w][b]; }
            tot[b] = s;
        }
        __syncthreads();

        if (warp == 0) {
            int sz = 0;
            if (lane < 16) sz = (tot[lane + 1] + 3) & ~3;
            int s = sz;
#pragma unroll
            for (int d = 1; d < 16; d <<= 1) {
                int t = __shfl_up_sync(0xffffffffu, s, d);
                if (lane >= d) s += t;
            }
            if (lane < 16) base[lane + 1] = s - sz;
            if (lane == 15) base[17] = s;
        }
        __syncthreads();

        unsigned short* hrow = g_hlist + (size_t)row * HL_PITCH;
        if (k > 0) {
            int pos = base[k] + wpre[warp][k] + rank;
            hrow[pos] = (unsigned short)h;
        }
        if (threadIdx.x < 16) {
            int b = threadIdx.x + 1;
            int sz = tot[b];
            int pad = (sz + 3) & ~3;
            for (int q = sz; q < pad; q++) hrow[base[b] + q] = 512;
        }
        if (threadIdx.x < 16)
            g_offs[(size_t)row * OF_PITCH + threadIdx.x + 1] =
                (unsigned short)base[threadIdx.x + 2];
        if (threadIdx.x == 16)
            g_offs[(size_t)row * OF_PITCH] = 0;
    }
}

// ---------------------------------------------------------------------------
// Kernel 3: (round-14 + depth-2 prefetch + m0) 1024 threads, warps fully
// independent after staging; direct uniform LDG.64 index reads with a
// 2-deep rolling prefetch (pitch-bounded: max idx+8 = 568 < 576).
// ---------------------------------------------------------------------------
#define W2T_PITCH 64
#define W2T_ROWS  513
#define W2T_BYTES (W2T_ROWS * W2T_PITCH * 4)   // 131328
#define TT_BYTES  (16 * 32 * 33 * 4)           // 67584
#define ROWS_PER_BLOCK 128
#define P2_SMEM_BYTES (W2T_BYTES + TT_BYTES)   // 198912

__global__ void __launch_bounds__(1024, 1) phase2_kernel(
    const float* __restrict__ W2,
    const float* __restrict__ b2,
    float* __restrict__ out,
    int m0)
{
    extern __shared__ char smem_raw[];
    float* W2Ts = (float*)smem_raw;                 // [513][64]
    float* TT   = (float*)(smem_raw + W2T_BYTES);   // transpose staging only

    const int tid    = threadIdx.x;
    const int w      = tid >> 5;
    const int lane   = tid & 31;
    const int o2     = lane * 2;
    const int o_base = blockIdx.y * 64;

    if (w < 16) {
        float* tile = TT + w * 32 * 33;
#pragma unroll
        for (int tt = 0; tt < 2; tt++) {
            const int t   = w + tt * 16;
            const int oo0 = (t & 1) * 32;
            const int hh0 = (t >> 1) * 32;
#pragma unroll
            for (int r = 0; r < 32; r++) {
                tile[r * 33 + lane] =
                    W2[(size_t)(o_base + oo0 + r) * HID + hh0 + lane];
            }
            __syncwarp();
#pragma unroll
            for (int r2 = 0; r2 < 32; r2++) {
                W2Ts[(hh0 + r2) * W2T_PITCH + oo0 + lane] = tile[lane * 33 + r2];
            }
            __syncwarp();
        }
    }
    if (tid < 64) W2Ts[512 * W2T_PITCH + tid] = 0.f;
    __syncthreads();

    const float2 bb = *(const float2*)&b2[o_base + o2];
    const float* W2o = W2Ts + o2;
    const int row0 = m0 + blockIdx.x * ROWS_PER_BLOCK;

#pragma unroll
    for (int rr = 0; rr < ROWS_PER_BLOCK / 32; rr++) {
        const int row = row0 + rr * 32 + w;
        const unsigned short* ml = g_hlist + (size_t)row * HL_PITCH;

        const uint4 oa = *(const uint4*)(g_offs + (size_t)row * OF_PITCH);
        const uint4 ob = *(const uint4*)(g_offs + (size_t)row * OF_PITCH + 8);
        const unsigned int oc = *(const unsigned int*)(g_offs + (size_t)row * OF_PITCH + 16);
        const unsigned int ow[9] = {oa.x, oa.y, oa.z, oa.w, ob.x, ob.y, ob.z, ob.w, oc};

        float2 Ck[16];
        int idx = 0;
        // depth-2 rolling prefetch across the whole (contiguous-bucket) row
        uint2 pk0 = *(const uint2*)ml;
        uint2 pk1 = *(const uint2*)(ml + 4);
#pragma unroll
        for (int k = 1; k <= TSTEPS; k++) {
            const int e = (int)((ow[k >> 1] >> ((k & 1) * 16)) & 0xFFFFu);
            unsigned long long accA = 0ull, accB = 0ull;
            for (; idx < e; idx += 4) {
                const uint2 cur = pk0;
                pk0 = pk1;
                pk1 = *(const uint2*)&ml[idx + 8];   // pitch-bounded
                int h0 = cur.x & 0xFFFF;
                int h1 = cur.x >> 16;
                int h2 = cur.y & 0xFFFF;
                int h3 = cur.y >> 16;
                unsigned long long w0 = *(const unsigned long long*)&W2o[h0 * W2T_PITCH];
                unsigned long long w1 = *(const unsigned long long*)&W2o[h1 * W2T_PITCH];
                unsigned long long w2 = *(const unsigned long long*)&W2o[h2 * W2T_PITCH];
                unsigned long long w3 = *(const unsigned long long*)&W2o[h3 * W2T_PITCH];
                addx2(accA, w0);
                addx2(accB, w1);
                addx2(accA, w2);
                addx2(accB, w3);
            }
            addx2(accA, accB);
            union { unsigned long long u; float2 f; } cvt;
            cvt.u = accA;
            Ck[k - 1] = cvt.f;
        }

        float m2x = 0.f, m2y = 0.f, scx = 0.f, scy = 0.f;
#pragma unroll
        for (int t = 1; t <= TSTEPS; t++) {
            float yx = 0.f, yy = 0.f;
#pragma unroll
            for (int d = 1; d <= TSTEPS; d++)
                if (t % d == 0) { yx += Ck[d - 1].x; yy += Ck[d - 1].y; }
            m2x = (m2x + yx) + bb.x;
            m2y = (m2y + yy) + bb.y;
            if (m2x > 0.5f) { scx += 1.f; m2x = 0.f; }
            if (m2y > 0.5f) { scy += 1.f; m2y = 0.f; }
        }
        float2 res = make_float2(scx * 0.0625f, scy * 0.0625f);
        *(float2*)&out[(size_t)row * OUT_DIM + o_base + o2] = res;
    }
}

// ---------------------------------------------------------------------------
// Launch: 2-chunk pipeline, fork/join via events (created lazily on the
// uncaptured correctness call; reused inside graph capture).
// ---------------------------------------------------------------------------
extern "C" void kernel_launch(void* const* d_in, const int* in_sizes, int n_in,
                              void* d_out, int out_size)
{
    const float* x  = (const float*)d_in[0];
    const float* W1 = (const float*)d_in[1];
    const float* b1 = (const float*)d_in[2];
    const float* W2 = (const float*)d_in[3];
    const float* b2 = (const float*)d_in[4];
    float* out = (float*)d_out;

    static cudaStream_t s2 = nullptr;
    static cudaEvent_t evG0 = nullptr, evP0 = nullptr;
    if (s2 == nullptr) {
        cudaStreamCreateWithFlags(&s2, cudaStreamNonBlocking);
        cudaEventCreateWithFlags(&evG0, cudaEventDisableTiming);
        cudaEventCreateWithFlags(&evP0, cudaEventDisableTiming);
    }

    cudaFuncSetAttribute(phase2_kernel,
                         cudaFuncAttributeMaxDynamicSharedMemorySize,
                         P2_SMEM_BYTES);

    dim3 g1(M_CHUNK / 128, HID / 256);
    dim3 g2(M_CHUNK / ROWS_PER_BLOCK, OUT_DIM / 64);
    const int bkg = M_CHUNK / BK_ROWS;

    // chunk 0 GEMM on main stream, then fork
    gemm1_kernel<<<g1, 256>>>(x, W1, b1, 0);
    cudaEventRecord(evG0, 0);

    // chunk 1 GEMM continues on main stream
    gemm1_kernel<<<g1, 256>>>(x, W1, b1, M_CHUNK);

    // side stream: chunk 0 bucketize + phase2 (overlaps gemm1 chunk 1)
    cudaStreamWaitEvent(s2, evG0, 0);
    bucketize_kernel<<<bkg, 512, 0, s2>>>(0);
    phase2_kernel<<<g2, 1024, P2_SMEM_BYTES, s2>>>(W2, b2, out, 0);
    cudaEventRecord(evP0, s2);

    // main stream: chunk 1 bucketize + phase2
    bucketize_kernel<<<bkg, 512>>>(M_CHUNK);
    phase2_kernel<<<g2, 1024, P2_SMEM_BYTES>>>(W2, b2, out, M_CHUNK);

    // join side stream back into main stream
    cudaStreamWaitEvent(0, evP0, 0);
}